// round 6
// baseline (speedup 1.0000x reference)
#include <cuda_runtime.h>

#define KS2      4
#define BASIS    8
#define HIDDEN   16
#define TS       4096
#define LOGIT_LO (-16.0f)
#define LOGIT_HI (16.0f)

// Piecewise-linear table of out = f(logit). Entry j = {f_j, f_{j+1} - f_j}.
__device__ float2 g_table[TS];

__device__ __forceinline__ float eval_f(float logit,
                                        const float* __restrict__ basis,
                                        const float* __restrict__ w1,
                                        const float* __restrict__ b1,
                                        const float* __restrict__ w2,
                                        const float* __restrict__ b2)
{
    // act = sigmoid(logit - THRESHOLD), THRESHOLD = 0
    float a = 1.0f / (1.0f + expf(-logit));

    float feats[BASIS];
#pragma unroll
    for (int b = 0; b < BASIS; ++b) {
        float s = 0.0f;
#pragma unroll
        for (int j = 0; j < KS2; ++j) {
            float d = a - basis[b * KS2 + j];
            s = fmaf(d, d, s);
        }
        feats[b] = expf(-s);   // GAMMA = 1
    }

    float out = b2[0];
#pragma unroll
    for (int i = 0; i < HIDDEN; ++i) {
        float h = b1[i];
#pragma unroll
        for (int b = 0; b < BASIS; ++b)
            h = fmaf(feats[b], w1[b * HIDDEN + i], h);
        out = fmaf(tanhf(h), w2[i], out);
    }
    return out;
}

__global__ void build_table_kernel(const float* __restrict__ basis,
                                   const float* __restrict__ w1,
                                   const float* __restrict__ b1,
                                   const float* __restrict__ w2,
                                   const float* __restrict__ b2)
{
    int j = blockIdx.x * blockDim.x + threadIdx.x;
    if (j >= TS) return;
    const float step = (LOGIT_HI - LOGIT_LO) / (float)(TS - 1);
    float x0 = LOGIT_LO + (float)j * step;
    float f0 = eval_f(x0, basis, w1, b1, w2, b2);
    float f1 = (j < TS - 1) ? eval_f(x0 + step, basis, w1, b1, w2, b2) : f0;
    g_table[j] = make_float2(f0, f1 - f0);
}

__device__ __forceinline__ float table_lookup_smem(const float2* __restrict__ tab,
                                                   float logit)
{
    const float scale = (float)(TS - 1) / (LOGIT_HI - LOGIT_LO);
    float u = (logit - LOGIT_LO) * scale;
    u = fminf(fmaxf(u, 0.0f), (float)(TS - 2));
    int j = (int)u;
    float frac = u - (float)j;
    float2 tv = tab[j];
    return fmaf(frac, tv.y, tv.x);
}

__global__ void __launch_bounds__(256)
patch_kernel(const float* __restrict__ data,
             const float* __restrict__ conv_w,
             const float* __restrict__ conv_b,
             float* __restrict__ out,
             int N)
{
    __shared__ float2 tab[TS];

    // Copy table (32 KB) from L2-resident global into shared memory.
    {
        const float4* gt = (const float4*)g_table;   // TS/2 float4s
#pragma unroll 4
        for (int i = threadIdx.x; i < TS / 2; i += 256) {
            float4 v = __ldg(gt + i);
            tab[2 * i + 0] = make_float2(v.x, v.y);
            tab[2 * i + 1] = make_float2(v.z, v.w);
        }
    }

    float cw0 = __ldg(conv_w + 0);
    float cw1 = __ldg(conv_w + 1);
    float cw2 = __ldg(conv_w + 2);
    float cw3 = __ldg(conv_w + 3);
    float cb  = __ldg(conv_b);

    __syncthreads();

    long long G      = (long long)N >> 2;                 // groups of 4 patches
    long long stride = (long long)gridDim.x * blockDim.x;

    for (long long g = (long long)blockIdx.x * blockDim.x + threadIdx.x;
         g < G; g += stride) {
        const float4* dp = (const float4*)data + g * 4;
        float r[4];
#pragma unroll
        for (int k = 0; k < 4; ++k) {
            float4 v = __ldg(dp + k);
            float logit = fmaf(v.x, cw0, fmaf(v.y, cw1, fmaf(v.z, cw2, fmaf(v.w, cw3, cb))));
            r[k] = table_lookup_smem(tab, logit);
        }
        ((float4*)out)[g] = make_float4(r[0], r[1], r[2], r[3]);
    }

    // Tail patches (N % 4) handled by one thread.
    if (blockIdx.x == 0 && threadIdx.x == 0) {
        for (long long i = G * 4; i < (long long)N; ++i) {
            float a0 = __ldg(data + i * 4 + 0);
            float a1 = __ldg(data + i * 4 + 1);
            float a2 = __ldg(data + i * 4 + 2);
            float a3 = __ldg(data + i * 4 + 3);
            float logit = fmaf(a0, cw0, fmaf(a1, cw1, fmaf(a2, cw2, fmaf(a3, cw3, cb))));
            out[i] = table_lookup_smem(tab, logit);
        }
    }
}

extern "C" void kernel_launch(void* const* d_in, const int* in_sizes, int n_in,
                              void* d_out, int out_size)
{
    const float* data   = (const float*)d_in[0];
    const float* conv_w = (const float*)d_in[1];
    const float* conv_b = (const float*)d_in[2];
    const float* basis  = (const float*)d_in[3];
    const float* w1     = (const float*)d_in[4];
    const float* b1     = (const float*)d_in[5];
    const float* w2     = (const float*)d_in[6];
    const float* b2     = (const float*)d_in[7];

    int N = in_sizes[0] / KS2;   // in_sizes[0] = N * KS * KS

    // 1) Build f(logit) table from this run's weights (deterministic).
    build_table_kernel<<<TS / 256, 256>>>(basis, w1, b1, w2, b2);

    // 2) Persistent streaming kernel: 7 CTAs/SM (32 KB smem each), grid-stride.
    int blocks = 148 * 7;
    long long G = (long long)N >> 2;
    long long maxb = (G + 255) / 256;
    if ((long long)blocks > maxb) blocks = (int)maxb;
    if (blocks < 1) blocks = 1;
    patch_kernel<<<blocks, 256>>>(data, conv_w, conv_b, (float*)d_out, N);
}